// round 9
// baseline (speedup 1.0000x reference)
#include <cuda_runtime.h>
#include <math.h>

// Problem constants (fixed: point_cloud [8, 4096, 3], K=20)
#define BATCH 8
#define NPTS  4096
#define KNN   20
#define TPB   512
#define WARPS (TPB / 32)          // 16 warps per CTA
#define CPB   37                  // CTAs per batch -> grid = 296 = 148 SMs * 2 (one wave)
#define FULLM 0xFFFFFFFFu

__global__ __launch_bounds__(TPB, 2)
void knn_warp_kernel(const float* __restrict__ pc, float* __restrict__ out)
{
    // Whole batch staged as float4 (x, y, z, |p|^2): 64 KB dynamic smem.
    extern __shared__ float4 pts[];
    __shared__ int qctr;

    const int b   = blockIdx.x / CPB;
    const int cta = blockIdx.x % CPB;
    const float* __restrict__ pcb = pc + (size_t)b * NPTS * 3;

    if (threadIdx.x == 0) qctr = 0;
    for (int i = threadIdx.x; i < NPTS; i += TPB) {
        float x = pcb[3 * i + 0];
        float y = pcb[3 * i + 1];
        float z = pcb[3 * i + 2];
        pts[i] = make_float4(x, y, z, fmaf(x, x, fmaf(y, y, z * z)));
    }
    __syncthreads();

    const int lane = threadIdx.x & 31;

    // Query range for this CTA (~110-111 queries), stolen in pairs by warps.
    const int qstart = (NPTS * cta) / CPB;
    const int qcount = (NPTS * (cta + 1)) / CPB - qstart;

    const long long BNK = (long long)BATCH * NPTS * KNN;
    float* __restrict__ srcA = out;
    float* __restrict__ tgtA = out + BNK;
    float* __restrict__ attA = out + 2 * BNK;
    float* __restrict__ slocA = out + 3 * BNK;

    for (;;) {
        int t;
        if (lane == 0) t = atomicAdd(&qctr, 2);
        t = __shfl_sync(FULLM, t, 0);
        if (t >= qcount) break;
        const bool hasB = (t + 1) < qcount;
        const int qiA = qstart + t;
        const int qiB = qstart + (hasB ? t + 1 : t);   // degenerate duplicate if odd

        const float4 qa = pts[qiA];
        const float4 qb = pts[qiB];
        const float axn = -2.0f * qa.x, ayn = -2.0f * qa.y, azn = -2.0f * qa.z;
        const float bxn = -2.0f * qb.x, byn = -2.0f * qb.y, bzn = -2.0f * qb.z;
        const float sqa = qa.w, sqb = qb.w;

        // Two independent lane-sorted lists: lane l = (l+1)-th smallest (d2, idx).
        // Exactness for lanes 0..21 via stale-threshold argument (see drain).
        float ldA, ldB;
        int   liA = lane, liB = lane;

        // ---- seed: exact bitonic sort of candidates 0..31 (both lists) ----
        {
            float4 p = pts[lane];
            float ta = fmaf(axn, p.x, fmaf(ayn, p.y, fmaf(azn, p.z, p.w)));
            float tb = fmaf(bxn, p.x, fmaf(byn, p.y, fmaf(bzn, p.z, p.w)));
            ldA = fmaxf(ta + sqa, 0.0f);
            ldB = fmaxf(tb + sqb, 0.0f);
        }
#pragma unroll
        for (int k = 2; k <= 32; k <<= 1) {
#pragma unroll
            for (int j = k >> 1; j > 0; j >>= 1) {
                bool up     = (lane & k) == 0;
                bool iLower = (lane & j) == 0;
                float odA = __shfl_xor_sync(FULLM, ldA, j);
                int   oiA = __shfl_xor_sync(FULLM, liA, j);
                float odB = __shfl_xor_sync(FULLM, ldB, j);
                int   oiB = __shfl_xor_sync(FULLM, liB, j);
                bool lessA = (odA < ldA) || ((odA == ldA) && (oiA < liA));
                bool lessB = (odB < ldB) || ((odB == ldB) && (oiB < liB));
                bool takeA = (iLower == up) ? lessA : !lessA;
                bool takeB = (iLower == up) ? lessB : !lessB;
                if (takeA) { ldA = odA; liA = oiA; }
                if (takeB) { ldB = odB; liB = oiB; }
            }
        }
        float thrA = __shfl_sync(FULLM, ldA, 21);
        float thrB = __shfl_sync(FULLM, ldB, 21);

        // Serial stable insert of one admitted candidate batch into a list.
        // Admission thr is conservative/stale; a candidate >= current lane-31
        // value yields all-false pred and is dropped -- provably outside the
        // exact top-22, so lanes 0..21 stay exact. Drain ascending index.
        auto drain = [&](unsigned m, float dval, int jbase, float& ldr, int& lir) {
            while (m) {
                int srcl = __ffs(m) - 1; m &= m - 1;
                float cd = __shfl_sync(FULLM, dval, srcl);
                int   cj = jbase + srcl;
                float ud = __shfl_up_sync(FULLM, ldr, 1);
                int   ui = __shfl_up_sync(FULLM, lir, 1);
                bool pred  = cd < ldr;                  // strict: stable ties
                bool predp = (lane > 0) && (cd < ud);
                if (pred) {
                    ldr = predp ? ud : cd;
                    lir = predp ? ui : cj;
                }
            }
        };

        // ---- half batch: candidates 32..63 (both queries) ----------------
        {
            float4 p = pts[32 + lane];
            float ta = fmaf(axn, p.x, fmaf(ayn, p.y, fmaf(azn, p.z, p.w)));
            float tb = fmaf(bxn, p.x, fmaf(byn, p.y, fmaf(bzn, p.z, p.w)));
            float da = fmaxf(ta + sqa, 0.0f);
            float db = fmaxf(tb + sqb, 0.0f);
            unsigned ma = __ballot_sync(FULLM, da < thrA);
            unsigned mb = __ballot_sync(FULLM, db < thrB);
            if (ma) { drain(ma, da, 32, ldA, liA); thrA = __shfl_sync(FULLM, ldA, 21); }
            if (mb) { drain(mb, db, 32, ldB, liB); thrB = __shfl_sync(FULLM, ldB, 21); }
        }

        // ---- full batches: candidates 64..4095 ---------------------------
#pragma unroll 2
        for (int s = 0; s < (NPTS - 64) / 64; s++) {
            const int j0 = 64 + s * 64;
            float4 p0 = pts[j0 + lane];
            float4 p1 = pts[j0 + 32 + lane];
            float t0a = fmaf(axn, p0.x, fmaf(ayn, p0.y, fmaf(azn, p0.z, p0.w)));
            float t1a = fmaf(axn, p1.x, fmaf(ayn, p1.y, fmaf(azn, p1.z, p1.w)));
            float t0b = fmaf(bxn, p0.x, fmaf(byn, p0.y, fmaf(bzn, p0.z, p0.w)));
            float t1b = fmaf(bxn, p1.x, fmaf(byn, p1.y, fmaf(bzn, p1.z, p1.w)));
            float d0a = fmaxf(t0a + sqa, 0.0f);
            float d1a = fmaxf(t1a + sqa, 0.0f);
            float d0b = fmaxf(t0b + sqb, 0.0f);
            float d1b = fmaxf(t1b + sqb, 0.0f);

            unsigned m0a = __ballot_sync(FULLM, d0a < thrA);
            unsigned m1a = __ballot_sync(FULLM, d1a < thrA);
            unsigned m0b = __ballot_sync(FULLM, d0b < thrB);
            unsigned m1b = __ballot_sync(FULLM, d1b < thrB);

            if (m0a | m1a) {
                drain(m0a, d0a, j0,      ldA, liA);
                drain(m1a, d1a, j0 + 32, ldA, liA);
                thrA = __shfl_sync(FULLM, ldA, 21);
            }
            if (m0b | m1b) {
                drain(m0b, d0b, j0,      ldB, liB);
                drain(m1b, d1b, j0 + 32, ldB, liB);
                thrB = __shfl_sync(FULLM, ldB, 21);
            }
        }

        // ---- epilogue: lane 0 = self; neighbors = lanes 1..20 ------------
        auto emit = [&](int qi, float ld, int li) {
            const int row = b * NPTS + qi;
            float dk2 = __shfl_sync(FULLM, ld, 20);
            float dk = sqrtf(dk2);
            float sigma = dk + 1e-6f;                 // BETA = 1
            float inv2s2 = 1.0f / (2.0f * sigma * sigma);
            const long long base = (long long)row * KNN;
            if (lane >= 1 && lane <= KNN) {
                int k = lane - 1;
                srcA[base + k] = (float)row;
                tgtA[base + k] = (float)(b * NPTS + li);
                attA[base + k] = expf(-ld * inv2s2);
            }
            if (lane == 0) slocA[row] = dk * dk;      // LAMBDA = 1
        };
        emit(qiA, ldA, liA);
        if (hasB) emit(qiB, ldB, liB);
    }
}

extern "C" void kernel_launch(void* const* d_in, const int* in_sizes, int n_in,
                              void* d_out, int out_size)
{
    (void)in_sizes; (void)n_in; (void)out_size;
    const float* pc = (const float*)d_in[0];
    float* outp = (float*)d_out;

    const size_t smem = (size_t)NPTS * sizeof(float4);   // 64 KB
    cudaFuncSetAttribute(knn_warp_kernel,
                         cudaFuncAttributeMaxDynamicSharedMemorySize, (int)smem);
    knn_warp_kernel<<<BATCH * CPB, TPB, smem>>>(pc, outp);
}

// round 10
// speedup vs baseline: 1.0168x; 1.0168x over previous
#include <cuda_runtime.h>
#include <math.h>

// Problem constants (fixed: point_cloud [8, 4096, 3], K=20)
#define BATCH 8
#define NPTS  4096
#define KNN   20
#define TPB   512
#define WARPS (TPB / 32)          // 16 warps per CTA
#define CPB   55                  // CTAs per batch -> grid = 440 (one balanced wave @3/SM)
#define FULLM 0xFFFFFFFFu
#define NPAIR (NPTS / 2)          // 2048 packed candidate pairs

typedef unsigned long long u64;

__device__ __forceinline__ u64 pk2(float lo, float hi) {
    u64 r; asm("mov.b64 %0, {%1, %2};" : "=l"(r) : "f"(lo), "f"(hi)); return r;
}
__device__ __forceinline__ void upk2(u64 v, float& lo, float& hi) {
    asm("mov.b64 {%0, %1}, %2;" : "=f"(lo), "=f"(hi) : "l"(v));
}
__device__ __forceinline__ u64 fma2(u64 a, u64 b, u64 c) {
    u64 r; asm("fma.rn.f32x2 %0, %1, %2, %3;" : "=l"(r) : "l"(a), "l"(b), "l"(c)); return r;
}

__global__ __launch_bounds__(TPB, 3)
void knn_warp_kernel(const float* __restrict__ pc, float* __restrict__ out)
{
    // Pair-packed staging (64 KB): pair i (i = s*64 + r, s<32, r<64) holds
    // candidates a = s*128 + r and b = a + 64:
    //   A[i] = (x_a, x_b, y_a, y_b),  Bp[i] = (z_a, z_b, w_a, w_b), w = |p|^2
    extern __shared__ float4 sh[];
    float4* __restrict__ A  = sh;
    float4* __restrict__ Bp = sh + NPAIR;
    __shared__ int qctr;

    const int b   = blockIdx.x / CPB;
    const int cta = blockIdx.x % CPB;
    const float* __restrict__ pcb = pc + (size_t)b * NPTS * 3;

    if (threadIdx.x == 0) qctr = 0;
    for (int i = threadIdx.x; i < NPAIR; i += TPB) {
        int s = i >> 6, r = i & 63;
        int a = s * 128 + r;
        int c = a + 64;
        float xa = pcb[3*a+0], ya = pcb[3*a+1], za = pcb[3*a+2];
        float xb = pcb[3*c+0], yb = pcb[3*c+1], zb = pcb[3*c+2];
        float wa = fmaf(xa, xa, fmaf(ya, ya, za * za));
        float wb = fmaf(xb, xb, fmaf(yb, yb, zb * zb));
        A[i]  = make_float4(xa, xb, ya, yb);
        Bp[i] = make_float4(za, zb, wa, wb);
    }
    __syncthreads();

    const int lane = threadIdx.x & 31;
    const int qstart = (NPTS * cta) / CPB;
    const int qcount = (NPTS * (cta + 1)) / CPB - qstart;

    const long long BNK = (long long)BATCH * NPTS * KNN;
    float* __restrict__ srcA  = out;
    float* __restrict__ tgtA  = out + BNK;
    float* __restrict__ attA  = out + 2 * BNK;
    float* __restrict__ slocA = out + 3 * BNK;

    for (;;) {
        int t;
        if (lane == 0) t = atomicAdd(&qctr, 1);
        t = __shfl_sync(FULLM, t, 0);
        if (t >= qcount) break;
        const int qi = qstart + t;

        // Query coords from the packed staging.
        float qx, qy, qz;
        {
            int s = qi >> 7, rm = qi & 127;
            int i = s * 64 + (rm & 63);
            float4 a0 = A[i], b0 = Bp[i];
            if (rm < 64) { qx = a0.x; qy = a0.z; qz = b0.x; }
            else         { qx = a0.y; qy = a0.w; qz = b0.y; }
        }
        const float nx = -2.0f * qx, ny = -2.0f * qy, nz = -2.0f * qz;
        const float sqq = fmaf(qx, qx, fmaf(qy, qy, qz * qz));
        const u64 nx2 = pk2(nx, nx), ny2 = pk2(ny, ny), nz2 = pk2(nz, nz);

        // Ranking key r = |p|^2 - 2 q.p  (= d^2 - |q|^2, monotone shift of d^2;
        // d^2 restored in the epilogue). Lane-sorted list: lane l = (l+1)-th
        // smallest (r, idx); exact for lanes 0..21 via the stale-threshold
        // argument (all-false pred => cand >= lane-31 value => outside top-22).
        float ld;
        int   li = lane;
        float r1s, r2s, r3s;                        // batch-0 leftovers
        {
            float4 a0 = A[lane],      b0 = Bp[lane];       // cands (lane, 64+lane)
            float4 a1 = A[32 + lane], b1 = Bp[32 + lane];  // cands (32+lane, 96+lane)
            u64 rA = fma2(nx2, pk2(a0.x, a0.y),
                     fma2(ny2, pk2(a0.z, a0.w),
                     fma2(nz2, pk2(b0.x, b0.y), pk2(b0.z, b0.w))));
            u64 rB = fma2(nx2, pk2(a1.x, a1.y),
                     fma2(ny2, pk2(a1.z, a1.w),
                     fma2(nz2, pk2(b1.x, b1.y), pk2(b1.z, b1.w))));
            float r0;
            upk2(rA, r0, r1s);
            upk2(rB, r2s, r3s);
            ld = r0;                                 // candidate 'lane' seeds sort
        }

        // ---- seed: exact bitonic sort of candidates 0..31 ----------------
#pragma unroll
        for (int k = 2; k <= 32; k <<= 1) {
#pragma unroll
            for (int j = k >> 1; j > 0; j >>= 1) {
                float od = __shfl_xor_sync(FULLM, ld, j);
                int   oi = __shfl_xor_sync(FULLM, li, j);
                bool up     = (lane & k) == 0;
                bool iLower = (lane & j) == 0;
                bool oless  = (od < ld) || ((od == ld) && (oi < li));
                bool take   = (iLower == up) ? oless : !oless;
                if (take) { ld = od; li = oi; }
            }
        }
        float thr = __shfl_sync(FULLM, ld, 21);

        // Stable serial insert of admitted candidates (ascending index).
        auto drain = [&](unsigned m, float dval, int jbase) {
            while (m) {
                int srcl = __ffs(m) - 1; m &= m - 1;
                float cd = __shfl_sync(FULLM, dval, srcl);
                int   cj = jbase + srcl;
                float ud = __shfl_up_sync(FULLM, ld, 1);
                int   ui = __shfl_up_sync(FULLM, li, 1);
                bool pred  = cd < ld;                 // strict: stable ties
                bool predp = (lane > 0) && (cd < ud);
                if (pred) {
                    ld = predp ? ud : cd;
                    li = predp ? ui : cj;
                }
            }
        };

        // ---- batch 0 remainder: candidates 32..127 -----------------------
        {
            float mmin = fminf(r2s, fminf(r1s, r3s));
            if (__ballot_sync(FULLM, mmin < thr)) {
                unsigned m2 = __ballot_sync(FULLM, r2s < thr);
                unsigned m1 = __ballot_sync(FULLM, r1s < thr);
                unsigned m3 = __ballot_sync(FULLM, r3s < thr);
                drain(m2, r2s, 32);
                drain(m1, r1s, 64);
                drain(m3, r3s, 96);
                thr = __shfl_sync(FULLM, ld, 21);
            }
        }

        // ---- main batches: 128 candidates each (s = 1..31) ---------------
#pragma unroll 2
        for (int s = 1; s < NPTS / 128; s++) {
            const int i0 = s * 64 + lane;
            float4 a0 = A[i0],      b0 = Bp[i0];        // (j0+l, j0+64+l)
            float4 a1 = A[i0 + 32], b1 = Bp[i0 + 32];   // (j0+32+l, j0+96+l)
            u64 rA = fma2(nx2, pk2(a0.x, a0.y),
                     fma2(ny2, pk2(a0.z, a0.w),
                     fma2(nz2, pk2(b0.x, b0.y), pk2(b0.z, b0.w))));
            u64 rB = fma2(nx2, pk2(a1.x, a1.y),
                     fma2(ny2, pk2(a1.z, a1.w),
                     fma2(nz2, pk2(b1.x, b1.y), pk2(b1.z, b1.w))));
            float r0, r1, r2, r3;
            upk2(rA, r0, r1);
            upk2(rB, r2, r3);

            float mmin = fminf(fminf(r0, r1), fminf(r2, r3));
            if (__ballot_sync(FULLM, mmin < thr)) {
                const int j0 = s * 128;
                unsigned m0 = __ballot_sync(FULLM, r0 < thr);
                unsigned m2 = __ballot_sync(FULLM, r2 < thr);
                unsigned m1 = __ballot_sync(FULLM, r1 < thr);
                unsigned m3 = __ballot_sync(FULLM, r3 < thr);
                drain(m0, r0, j0);
                drain(m2, r2, j0 + 32);
                drain(m1, r1, j0 + 64);
                drain(m3, r3, j0 + 96);
                thr = __shfl_sync(FULLM, ld, 21);
            }
        }

        // ---- epilogue: lane 0 = self (r strictly minimal); lanes 1..20 ---
        const int row = b * NPTS + qi;
        float d2l = fmaxf(ld + sqq, 0.0f);             // back to true d^2
        float dk2 = __shfl_sync(FULLM, d2l, 20);       // k-th neighbor d^2
        float dk = sqrtf(dk2);
        float sigma = dk + 1e-6f;                      // BETA = 1
        float inv2s2 = 1.0f / (2.0f * sigma * sigma);

        const long long base = (long long)row * KNN;
        if (lane >= 1 && lane <= KNN) {
            int k = lane - 1;
            srcA[base + k] = (float)row;
            tgtA[base + k] = (float)(b * NPTS + li);
            attA[base + k] = expf(-d2l * inv2s2);
        }
        if (lane == 0) slocA[row] = dk * dk;           // LAMBDA = 1
    }
}

extern "C" void kernel_launch(void* const* d_in, const int* in_sizes, int n_in,
                              void* d_out, int out_size)
{
    (void)in_sizes; (void)n_in; (void)out_size;
    const float* pc = (const float*)d_in[0];
    float* outp = (float*)d_out;

    const size_t smem = (size_t)NPTS * sizeof(float4);   // 64 KB
    cudaFuncSetAttribute(knn_warp_kernel,
                         cudaFuncAttributeMaxDynamicSharedMemorySize, (int)smem);
    knn_warp_kernel<<<BATCH * CPB, TPB, smem>>>(pc, outp);
}